// round 16
// baseline (speedup 1.0000x reference)
#include <cuda_runtime.h>
#include <cuda_fp16.h>
#include <math.h>
#include <stdint.h>

#define BB 4
#define TT 8192
#define DD 512
#define HH 512
#define M_TOTAL (BB*TT)        // 32768
#define NC 128                 // scan chunks
#define CL (TT/NC)             // 64 steps per chunk
#define NCH (BB*HH)            // 2048 channels

// ---------------- device scratch (allocation-free) ----------------
__device__ __half2 g_fv[(size_t)M_TOTAL*HH];  // packed {f, v}, 64MB
__device__ __half  g_x[(size_t)M_TOTAL*DD];   // fp16 x, 32MB
__device__ __half  g_w[3*DD*HH];              // [g][n][k] transposed, fp16
__device__ float   g_cF[(size_t)NCH*NC];      // [channel][chunk]
__device__ float   g_cV[(size_t)NCH*NC];      // [channel][chunk]
__device__ float   g_hin[(size_t)NC*NCH];     // [chunk][channel]

__device__ __forceinline__ uint32_t smem_u32(const void* p) {
    uint32_t a;
    asm("{ .reg .u64 t; cvta.to.shared.u64 t, %1; cvt.u32.u64 %0, t; }" : "=r"(a) : "l"(p));
    return a;
}

#define LDM_X4(r0,r1,r2,r3,addr) \
    asm volatile("ldmatrix.sync.aligned.m8n8.x4.shared.b16 {%0,%1,%2,%3}, [%4];" \
        : "=r"(r0),"=r"(r1),"=r"(r2),"=r"(r3) : "r"(addr))

#define MMA_FP16(c,a,b) \
    asm volatile("mma.sync.aligned.m16n8k16.row.col.f32.f16.f16.f32 " \
        "{%0,%1,%2,%3},{%4,%5,%6,%7},{%8,%9},{%0,%1,%2,%3};" \
        : "+f"((c)[0]),"+f"((c)[1]),"+f"((c)[2]),"+f"((c)[3]) \
        : "r"((a)[0]),"r"((a)[1]),"r"((a)[2]),"r"((a)[3]),"r"((b)[0]),"r"((b)[1]))

struct alignas(8)  h2x2 { __half2 a, b; };
struct alignas(16) h2x4 { __half2 a, b, c, d; };

// ---------------------------------------------------------------------------
// Prep 1: convert x to fp16  (exact R14)
// ---------------------------------------------------------------------------
__global__ __launch_bounds__(256)
void cvt_x_kernel(const float* __restrict__ x) {
    size_t i = ((size_t)blockIdx.x * 256 + threadIdx.x) * 8;
    float4 v0 = *(const float4*)(x + i);
    float4 v1 = *(const float4*)(x + i + 4);
    h2x4 o;
    o.a = __floats2half2_rn(v0.x, v0.y);
    o.b = __floats2half2_rn(v0.z, v0.w);
    o.c = __floats2half2_rn(v1.x, v1.y);
    o.d = __floats2half2_rn(v1.z, v1.w);
    *(h2x4*)(g_x + i) = o;
}

// ---------------------------------------------------------------------------
// Prep 2: transpose W to fp16, layout [g][n][k]  (exact R14)
// ---------------------------------------------------------------------------
__global__ __launch_bounds__(256)
void split_w_kernel(const float* __restrict__ Wf, const float* __restrict__ Wi,
                    const float* __restrict__ Wh) {
    __shared__ float t[32][33];
    const float* W = (blockIdx.z == 0) ? Wf : (blockIdx.z == 1) ? Wi : Wh;
    int k0 = blockIdx.x * 32, n0 = blockIdx.y * 32;
    for (int i = threadIdx.y; i < 32; i += 8)
        t[i][threadIdx.x] = W[(size_t)(k0 + i) * HH + n0 + threadIdx.x];
    __syncthreads();
    for (int i = threadIdx.y; i < 32; i += 8) {
        size_t o = (size_t)blockIdx.z * DD * HH + (size_t)(n0 + i) * DD + k0 + threadIdx.x;
        g_w[o] = __float2half(t[threadIdx.x][i]);
    }
}

// ---------------------------------------------------------------------------
// Gate math: u=1+e^{-f_pre}, w=1+e^{-i_pre}: fg=w/(u+w), ig=u/(u+w)
//            g(x)= x>=0 ? x+0.5 : sigmoid(x);  v = ig*g(h_pre)
// ---------------------------------------------------------------------------
__device__ __forceinline__ void gate_fv(float fpre, float ipre, float hpre,
                                        float& f, float& v) {
    float u = 1.f + __expf(-fpre);
    float w = 1.f + __expf(-ipre);
    float r = __fdividef(1.f, u + w);
    f = w * r;
    float ig = u * r;
    float g = (hpre >= 0.f) ? (hpre + 0.5f)
                            : __fdividef(1.f, 1.f + __expf(-hpre));
    v = ig * g;
}

// ---------------------------------------------------------------------------
// Kernel 1: fused 3-gate fp16 GEMM + gate epilogue + in-epilogue chunk scan.
// (exact R14 — fp32 accumulation, at legacy-HMMA floor)
// ---------------------------------------------------------------------------
#define NKT    8                     // 512 / 64
#define STAGES 3
#define PITCH  144                   // 128B data + 16B pad; conflict-free
#define ROWS_ST 224                  // 128 (x) + 96 (W: 3g x 32h)
#define STAGE_BYTES (ROWS_ST*PITCH)  // 32256
#define GEMM_SMEM (STAGES*STAGE_BYTES)  // 96768
#define OFF_B   (128*PITCH)

__global__ __launch_bounds__(256, 2)
void gemm_mma_kernel(const float* __restrict__ bf_, const float* __restrict__ bi_,
                     const float* __restrict__ bh_) {
    extern __shared__ char sm[];
    const uint32_t sb = smem_u32(sm);
    const int tid = threadIdx.x;
    const int m0 = blockIdx.y * 128;
    const int h0 = blockIdx.x * 32;

    const int wid = tid >> 5, lane = tid & 31;
    const int wm = wid & 3, wn = wid >> 2;      // 4m x 2n warps; warp 32m x 16h x 3g
    const int grp = lane >> 3, lrow = lane & 7;

    float acc[3][2][2][4];
    #pragma unroll
    for (int g = 0; g < 3; g++)
        #pragma unroll
        for (int mt = 0; mt < 2; mt++)
            #pragma unroll
            for (int nt = 0; nt < 2; nt++)
                #pragma unroll
                for (int j = 0; j < 4; j++) acc[g][mt][nt][j] = 0.f;

    auto issue = [&](int kt) {
        const uint32_t sst = sb + (kt % STAGES) * STAGE_BYTES;
        const int kin = kt * 64;
        #pragma unroll
        for (int i = tid; i < 1792; i += 256) {
            int r = i >> 3, c = i & 7;
            const __half* src;
            if (r < 128) src = g_x + (size_t)(m0 + r) * 512 + kin;
            else {
                int rr = r - 128;
                src = g_w + (size_t)(rr >> 5) * DD * HH
                          + (size_t)(h0 + (rr & 31)) * 512 + kin;
            }
            asm volatile("cp.async.cg.shared.global [%0], [%1], 16;"
                         :: "r"(sst + r * PITCH + c * 16), "l"(src + c * 8));
        }
        asm volatile("cp.async.commit_group;" ::: "memory");
    };

    issue(0); issue(1);

    #pragma unroll 1
    for (int kt = 0; kt < NKT; kt++) {
        asm volatile("cp.async.wait_group 1;" ::: "memory");
        __syncthreads();
        if (kt + 2 < NKT) issue(kt + 2);

        const uint32_t sst = sb + (kt % STAGES) * STAGE_BYTES;

        #pragma unroll
        for (int kk = 0; kk < 4; kk++) {
            const uint32_t acol = (uint32_t)(kk * 2 + (grp >> 1)) * 16;
            const uint32_t bcol = (uint32_t)(kk * 2 + (grp & 1)) * 16;
            uint32_t a[2][4];
            #pragma unroll
            for (int mt = 0; mt < 2; mt++) {
                uint32_t rrow = (uint32_t)(wm * 32 + mt * 16 + lrow + (grp & 1) * 8) * PITCH;
                LDM_X4(a[mt][0], a[mt][1], a[mt][2], a[mt][3], sst + rrow + acol);
            }
            uint32_t b[3][2][2];
            #pragma unroll
            for (int g = 0; g < 3; g++) {
                uint32_t addr = sst + OFF_B
                    + (uint32_t)(g * 32 + wn * 16 + lrow + (grp >> 1) * 8) * PITCH + bcol;
                uint32_t r0, r1, r2, r3;
                LDM_X4(r0, r1, r2, r3, addr);
                b[g][0][0] = r0; b[g][0][1] = r1;
                b[g][1][0] = r2; b[g][1][1] = r3;
            }
            #pragma unroll
            for (int g = 0; g < 3; g++)
                #pragma unroll
                for (int mt = 0; mt < 2; mt++)
                    #pragma unroll
                    for (int nt = 0; nt < 2; nt++)
                        MMA_FP16(acc[g][mt][nt], a[mt], b[g][nt]);
        }
    }

    // --- epilogue: gate math, write packed {f,v}, keep values for reduction ---
    float fr[2][2][2][2], vr[2][2][2][2];   // [mt][nt][half][col]
    #pragma unroll
    for (int mt = 0; mt < 2; mt++) {
        #pragma unroll
        for (int nt = 0; nt < 2; nt++) {
            const int m = m0 + wm * 32 + mt * 16 + (lane >> 2);
            const int h = h0 + wn * 16 + nt * 8 + 2 * (lane & 3);
            const float b0f = __ldg(&bf_[h]), b1f = __ldg(&bf_[h + 1]);
            const float b0i = __ldg(&bi_[h]), b1i = __ldg(&bi_[h + 1]);
            const float b0h = __ldg(&bh_[h]), b1h = __ldg(&bh_[h + 1]);
            #pragma unroll
            for (int half_ = 0; half_ < 2; half_++) {      // rows m, m+8
                const int mm = m + half_ * 8;
                float f0, v0, f1, v1;
                gate_fv(acc[0][mt][nt][half_*2+0] + b0f,
                        acc[1][mt][nt][half_*2+0] + b0i,
                        acc[2][mt][nt][half_*2+0] + b0h, f0, v0);
                gate_fv(acc[0][mt][nt][half_*2+1] + b1f,
                        acc[1][mt][nt][half_*2+1] + b1i,
                        acc[2][mt][nt][half_*2+1] + b1h, f1, v1);
                fr[mt][nt][half_][0] = f0; vr[mt][nt][half_][0] = v0;
                fr[mt][nt][half_][1] = f1; vr[mt][nt][half_][1] = v1;
                h2x2 pk;
                pk.a = __floats2half2_rn(f0, v0);
                pk.b = __floats2half2_rn(f1, v1);
                *(h2x2*)&g_fv[(size_t)mm * HH + h] = pk;
            }
        }
    }

    // --- in-epilogue chunk scan: t = 32*wm + 16*mt + 8*half + (lane>>2) ---
    // compose(early, late): F = F1*F2, V = F2*V1 + V2
    __syncthreads();                         // pipeline smem fully consumed
    float* sF = (float*)sm;                  // [4 warps][32 ch]
    float* sV = (float*)(sm + 512);
    #pragma unroll
    for (int nt = 0; nt < 2; nt++) {
        #pragma unroll
        for (int col = 0; col < 2; col++) {
            float F[2][2], V[2][2];          // [mt][half]
            #pragma unroll
            for (int mt = 0; mt < 2; mt++)
                #pragma unroll
                for (int hf = 0; hf < 2; hf++) {
                    F[mt][hf] = fr[mt][nt][hf][col];
                    V[mt][hf] = vr[mt][nt][hf][col];
                }
            // 3 xor-shuffle rounds over r8 (consecutive t within runs of 8)
            #pragma unroll
            for (int s = 0; s < 3; s++) {
                const int msk = 4 << s;
                const bool up = (lane & msk) != 0;   // higher r8 = later t
                #pragma unroll
                for (int mt = 0; mt < 2; mt++)
                    #pragma unroll
                    for (int hf = 0; hf < 2; hf++) {
                        float Fo = __shfl_xor_sync(0xFFFFFFFFu, F[mt][hf], msk);
                        float Vo = __shfl_xor_sync(0xFFFFFFFFu, V[mt][hf], msk);
                        float FL = up ? Fo : F[mt][hf];
                        float VL = up ? Vo : V[mt][hf];
                        float FH = up ? F[mt][hf] : Fo;
                        float VH = up ? V[mt][hf] : Vo;
                        F[mt][hf] = FL * FH;
                        V[mt][hf] = fmaf(VL, FH, VH);
                    }
            }
            // within thread, t order: (mt=0,hf=0),(0,1),(1,0),(1,1)
            float F01 = F[0][0] * F[0][1];
            float V01 = fmaf(V[0][0], F[0][1], V[0][1]);
            float F23 = F[1][0] * F[1][1];
            float V23 = fmaf(V[1][0], F[1][1], V[1][1]);
            float Fw = F01 * F23;
            float Vw = fmaf(V01, F23, V23);   // per-warp run of 32 t
            if (lane < 4) {
                int ch = wn * 16 + nt * 8 + 2 * lane + col;
                sF[wm * 32 + ch] = Fw;
                sV[wm * 32 + ch] = Vw;
            }
        }
    }
    __syncthreads();
    if (tid < 64) {                          // 2 chunks x 32 channels
        const int ch = tid & 31, p = tid >> 5;
        float F1 = sF[(2*p)   * 32 + ch], V1 = sV[(2*p)   * 32 + ch];
        float F2 = sF[(2*p+1) * 32 + ch], V2 = sV[(2*p+1) * 32 + ch];
        const int b = m0 >> 13;                        // m0 / TT
        const int chunk = ((m0 & (TT - 1)) >> 6) + p;  // t0/64 + p
        // transposed layout: [channel][chunk]
        const size_t o = (size_t)(b * HH + h0 + ch) * NC + chunk;
        g_cF[o] = F1 * F2;
        g_cV[o] = fmaf(V1, F2, V2);
    }
}

// ---------------------------------------------------------------------------
// Kernel 3: PARALLEL cross-chunk scan (exact R14 — coalesced aggregates)
// ---------------------------------------------------------------------------
__global__ __launch_bounds__(128)
void scan_top_kernel(const float* __restrict__ h0, float* __restrict__ out) {
    const int ch = blockIdx.x;
    const int b = ch >> 9, hh = ch & (HH - 1);
    const int c = threadIdx.x;             // chunk 0..127
    const int lane = c & 31, w = c >> 5;
    __shared__ float sF[4], sV[4];

    float x = h0[(size_t)b * HH + hh];
    float h = (x >= 0.f) ? (x + 0.5f) : __fdividef(1.f, 1.f + __expf(-x));
    if (c == 0) out[(size_t)b * (TT + 1) * HH + hh] = h;

    const size_t oa = (size_t)ch * NC + c;   // coalesced along threadIdx
    float F = g_cF[oa], V = g_cV[oa];

    #pragma unroll
    for (int s = 1; s < 32; s <<= 1) {
        float Fo = __shfl_up_sync(0xFFFFFFFFu, F, s);
        float Vo = __shfl_up_sync(0xFFFFFFFFu, V, s);
        if (lane >= s) { V = fmaf(Vo, F, V); F = Fo * F; }
    }
    if (lane == 31) { sF[w] = F; sV[w] = V; }
    __syncthreads();

    float Pf = 1.f, Pv = 0.f;
    #pragma unroll
    for (int i = 0; i < 3; i++)
        if (w > i) { Pv = fmaf(Pv, sF[i], sV[i]); Pf = Pf * sF[i]; }

    float Fe = __shfl_up_sync(0xFFFFFFFFu, F, 1);
    float Ve = __shfl_up_sync(0xFFFFFFFFu, V, 1);
    if (lane == 0) { Fe = 1.f; Ve = 0.f; }

    float Fx = Pf * Fe;
    float Vx = fmaf(Pv, Fe, Ve);
    g_hin[(size_t)c * NCH + ch] = fmaf(Fx, h, Vx);   // [chunk][channel]
}

// ---------------------------------------------------------------------------
// Kernel 4: apply (R14 shape; __stcs on the write-once output to keep
// g_fv L2-resident)
// ---------------------------------------------------------------------------
__global__ __launch_bounds__(256)
void scan_apply_kernel(float* __restrict__ out) {
    const int ch = blockIdx.x * 256 + threadIdx.x;
    const int b = ch >> 9, hh = ch & (HH - 1);
    const int chunk = blockIdx.y;
    const int t0 = chunk * CL;
    const size_t gbase = ((size_t)b * TT + t0) * HH + hh;
    const size_t obase = ((size_t)b * (TT + 1) + t0 + 1) * HH + hh;

    float h = g_hin[(size_t)chunk * NCH + ch];
    #pragma unroll 8
    for (int t = 0; t < CL; t++) {
        float2 fv = __half22float2(g_fv[gbase + (size_t)t * HH]);
        h = fmaf(fv.x, h, fv.y);
        __stcs(&out[obase + (size_t)t * HH], h);
    }
}

// ---------------------------------------------------------------------------
extern "C" void kernel_launch(void* const* d_in, const int* in_sizes, int n_in,
                              void* d_out, int out_size) {
    const float* x  = (const float*)d_in[0];
    const float* h0 = (const float*)d_in[1];
    const float* Wf = (const float*)d_in[2];
    const float* bf = (const float*)d_in[3];
    const float* Wi = (const float*)d_in[4];
    const float* bi = (const float*)d_in[5];
    const float* Wh = (const float*)d_in[6];
    const float* bh = (const float*)d_in[7];
    float* out = (float*)d_out;

    cudaFuncSetAttribute(gemm_mma_kernel,
                         cudaFuncAttributeMaxDynamicSharedMemorySize, GEMM_SMEM);

    cvt_x_kernel<<<(size_t)M_TOTAL * DD / 8 / 256, 256>>>(x);
    {
        dim3 g(DD / 32, HH / 32, 3);
        split_w_kernel<<<g, dim3(32, 8)>>>(Wf, Wi, Wh);
    }
    {
        dim3 g(HH / 32, M_TOTAL / 128);    // (16, 256)
        gemm_mma_kernel<<<g, 256, GEMM_SMEM>>>(bf, bi, bh);
    }
    scan_top_kernel<<<NCH, 128>>>(h0, out);
    scan_apply_kernel<<<dim3(NCH / 256, NC), 256>>>(out);  // (8, 128)
}

// round 17
// speedup vs baseline: 1.0747x; 1.0747x over previous
#include <cuda_runtime.h>
#include <cuda_fp16.h>
#include <math.h>
#include <stdint.h>

#define BB 4
#define TT 8192
#define DD 512
#define HH 512
#define M_TOTAL (BB*TT)        // 32768
#define NC 128                 // scan chunks
#define CL (TT/NC)             // 64 steps per chunk
#define NCH (BB*HH)            // 2048 channels

// ---------------- device scratch (allocation-free) ----------------
__device__ __half2 g_fv[(size_t)M_TOTAL*HH];  // packed {f, v}, 64MB
__device__ __half  g_x[(size_t)M_TOTAL*DD];   // fp16 x, 32MB
__device__ __half  g_w[3*DD*HH];              // [g][n][k] transposed, fp16
__device__ float   g_cF[(size_t)NCH*NC];      // [channel][chunk]
__device__ float   g_cV[(size_t)NCH*NC];      // [channel][chunk]
__device__ float   g_hin[(size_t)NC*NCH];     // [chunk][channel]

__device__ __forceinline__ uint32_t smem_u32(const void* p) {
    uint32_t a;
    asm("{ .reg .u64 t; cvta.to.shared.u64 t, %1; cvt.u32.u64 %0, t; }" : "=r"(a) : "l"(p));
    return a;
}

#define LDM_X4(r0,r1,r2,r3,addr) \
    asm volatile("ldmatrix.sync.aligned.m8n8.x4.shared.b16 {%0,%1,%2,%3}, [%4];" \
        : "=r"(r0),"=r"(r1),"=r"(r2),"=r"(r3) : "r"(addr))

#define MMA_FP16(c,a,b) \
    asm volatile("mma.sync.aligned.m16n8k16.row.col.f32.f16.f16.f32 " \
        "{%0,%1,%2,%3},{%4,%5,%6,%7},{%8,%9},{%0,%1,%2,%3};" \
        : "+f"((c)[0]),"+f"((c)[1]),"+f"((c)[2]),"+f"((c)[3]) \
        : "r"((a)[0]),"r"((a)[1]),"r"((a)[2]),"r"((a)[3]),"r"((b)[0]),"r"((b)[1]))

struct alignas(8)  h2x2 { __half2 a, b; };
struct alignas(16) h2x4 { __half2 a, b, c, d; };

// ---------------------------------------------------------------------------
// Prep 1: convert x to fp16
// ---------------------------------------------------------------------------
__global__ __launch_bounds__(256)
void cvt_x_kernel(const float* __restrict__ x) {
    size_t i = ((size_t)blockIdx.x * 256 + threadIdx.x) * 8;
    float4 v0 = *(const float4*)(x + i);
    float4 v1 = *(const float4*)(x + i + 4);
    h2x4 o;
    o.a = __floats2half2_rn(v0.x, v0.y);
    o.b = __floats2half2_rn(v0.z, v0.w);
    o.c = __floats2half2_rn(v1.x, v1.y);
    o.d = __floats2half2_rn(v1.z, v1.w);
    *(h2x4*)(g_x + i) = o;
}

// ---------------------------------------------------------------------------
// Prep 2: transpose W to fp16, layout [g][n][k]
// ---------------------------------------------------------------------------
__global__ __launch_bounds__(256)
void split_w_kernel(const float* __restrict__ Wf, const float* __restrict__ Wi,
                    const float* __restrict__ Wh) {
    __shared__ float t[32][33];
    const float* W = (blockIdx.z == 0) ? Wf : (blockIdx.z == 1) ? Wi : Wh;
    int k0 = blockIdx.x * 32, n0 = blockIdx.y * 32;
    for (int i = threadIdx.y; i < 32; i += 8)
        t[i][threadIdx.x] = W[(size_t)(k0 + i) * HH + n0 + threadIdx.x];
    __syncthreads();
    for (int i = threadIdx.y; i < 32; i += 8) {
        size_t o = (size_t)blockIdx.z * DD * HH + (size_t)(n0 + i) * DD + k0 + threadIdx.x;
        g_w[o] = __float2half(t[threadIdx.x][i]);
    }
}

// ---------------------------------------------------------------------------
// Gate math: u=1+e^{-f_pre}, w=1+e^{-i_pre}: fg=w/(u+w), ig=u/(u+w)
//            g(x)= x>=0 ? x+0.5 : sigmoid(x);  v = ig*g(h_pre)
// ---------------------------------------------------------------------------
__device__ __forceinline__ void gate_fv(float fpre, float ipre, float hpre,
                                        float& f, float& v) {
    float u = 1.f + __expf(-fpre);
    float w = 1.f + __expf(-ipre);
    float r = __fdividef(1.f, u + w);
    f = w * r;
    float ig = u * r;
    float g = (hpre >= 0.f) ? (hpre + 0.5f)
                            : __fdividef(1.f, 1.f + __expf(-hpre));
    v = ig * g;
}

// ---------------------------------------------------------------------------
// Kernel 1: fused 3-gate fp16 GEMM + gate epilogue + in-epilogue chunk scan.
// (exact R14 — fp32 accumulation, at legacy-HMMA floor)
// ---------------------------------------------------------------------------
#define NKT    8                     // 512 / 64
#define STAGES 3
#define PITCH  144                   // 128B data + 16B pad; conflict-free
#define ROWS_ST 224                  // 128 (x) + 96 (W: 3g x 32h)
#define STAGE_BYTES (ROWS_ST*PITCH)  // 32256
#define GEMM_SMEM (STAGES*STAGE_BYTES)  // 96768
#define OFF_B   (128*PITCH)

__global__ __launch_bounds__(256, 2)
void gemm_mma_kernel(const float* __restrict__ bf_, const float* __restrict__ bi_,
                     const float* __restrict__ bh_) {
    extern __shared__ char sm[];
    const uint32_t sb = smem_u32(sm);
    const int tid = threadIdx.x;
    const int m0 = blockIdx.y * 128;
    const int h0 = blockIdx.x * 32;

    const int wid = tid >> 5, lane = tid & 31;
    const int wm = wid & 3, wn = wid >> 2;      // 4m x 2n warps; warp 32m x 16h x 3g
    const int grp = lane >> 3, lrow = lane & 7;

    float acc[3][2][2][4];
    #pragma unroll
    for (int g = 0; g < 3; g++)
        #pragma unroll
        for (int mt = 0; mt < 2; mt++)
            #pragma unroll
            for (int nt = 0; nt < 2; nt++)
                #pragma unroll
                for (int j = 0; j < 4; j++) acc[g][mt][nt][j] = 0.f;

    auto issue = [&](int kt) {
        const uint32_t sst = sb + (kt % STAGES) * STAGE_BYTES;
        const int kin = kt * 64;
        #pragma unroll
        for (int i = tid; i < 1792; i += 256) {
            int r = i >> 3, c = i & 7;
            const __half* src;
            if (r < 128) src = g_x + (size_t)(m0 + r) * 512 + kin;
            else {
                int rr = r - 128;
                src = g_w + (size_t)(rr >> 5) * DD * HH
                          + (size_t)(h0 + (rr & 31)) * 512 + kin;
            }
            asm volatile("cp.async.cg.shared.global [%0], [%1], 16;"
                         :: "r"(sst + r * PITCH + c * 16), "l"(src + c * 8));
        }
        asm volatile("cp.async.commit_group;" ::: "memory");
    };

    issue(0); issue(1);

    #pragma unroll 1
    for (int kt = 0; kt < NKT; kt++) {
        asm volatile("cp.async.wait_group 1;" ::: "memory");
        __syncthreads();
        if (kt + 2 < NKT) issue(kt + 2);

        const uint32_t sst = sb + (kt % STAGES) * STAGE_BYTES;

        #pragma unroll
        for (int kk = 0; kk < 4; kk++) {
            const uint32_t acol = (uint32_t)(kk * 2 + (grp >> 1)) * 16;
            const uint32_t bcol = (uint32_t)(kk * 2 + (grp & 1)) * 16;
            uint32_t a[2][4];
            #pragma unroll
            for (int mt = 0; mt < 2; mt++) {
                uint32_t rrow = (uint32_t)(wm * 32 + mt * 16 + lrow + (grp & 1) * 8) * PITCH;
                LDM_X4(a[mt][0], a[mt][1], a[mt][2], a[mt][3], sst + rrow + acol);
            }
            uint32_t b[3][2][2];
            #pragma unroll
            for (int g = 0; g < 3; g++) {
                uint32_t addr = sst + OFF_B
                    + (uint32_t)(g * 32 + wn * 16 + lrow + (grp >> 1) * 8) * PITCH + bcol;
                uint32_t r0, r1, r2, r3;
                LDM_X4(r0, r1, r2, r3, addr);
                b[g][0][0] = r0; b[g][0][1] = r1;
                b[g][1][0] = r2; b[g][1][1] = r3;
            }
            #pragma unroll
            for (int g = 0; g < 3; g++)
                #pragma unroll
                for (int mt = 0; mt < 2; mt++)
                    #pragma unroll
                    for (int nt = 0; nt < 2; nt++)
                        MMA_FP16(acc[g][mt][nt], a[mt], b[g][nt]);
        }
    }

    // --- epilogue: gate math, write packed {f,v}, keep values for reduction ---
    float fr[2][2][2][2], vr[2][2][2][2];   // [mt][nt][half][col]
    #pragma unroll
    for (int mt = 0; mt < 2; mt++) {
        #pragma unroll
        for (int nt = 0; nt < 2; nt++) {
            const int m = m0 + wm * 32 + mt * 16 + (lane >> 2);
            const int h = h0 + wn * 16 + nt * 8 + 2 * (lane & 3);
            const float b0f = __ldg(&bf_[h]), b1f = __ldg(&bf_[h + 1]);
            const float b0i = __ldg(&bi_[h]), b1i = __ldg(&bi_[h + 1]);
            const float b0h = __ldg(&bh_[h]), b1h = __ldg(&bh_[h + 1]);
            #pragma unroll
            for (int half_ = 0; half_ < 2; half_++) {      // rows m, m+8
                const int mm = m + half_ * 8;
                float f0, v0, f1, v1;
                gate_fv(acc[0][mt][nt][half_*2+0] + b0f,
                        acc[1][mt][nt][half_*2+0] + b0i,
                        acc[2][mt][nt][half_*2+0] + b0h, f0, v0);
                gate_fv(acc[0][mt][nt][half_*2+1] + b1f,
                        acc[1][mt][nt][half_*2+1] + b1i,
                        acc[2][mt][nt][half_*2+1] + b1h, f1, v1);
                fr[mt][nt][half_][0] = f0; vr[mt][nt][half_][0] = v0;
                fr[mt][nt][half_][1] = f1; vr[mt][nt][half_][1] = v1;
                h2x2 pk;
                pk.a = __floats2half2_rn(f0, v0);
                pk.b = __floats2half2_rn(f1, v1);
                *(h2x2*)&g_fv[(size_t)mm * HH + h] = pk;
            }
        }
    }

    // --- in-epilogue chunk scan: t = 32*wm + 16*mt + 8*half + (lane>>2) ---
    // compose(early, late): F = F1*F2, V = F2*V1 + V2
    __syncthreads();                         // pipeline smem fully consumed
    float* sF = (float*)sm;                  // [4 warps][32 ch]
    float* sV = (float*)(sm + 512);
    #pragma unroll
    for (int nt = 0; nt < 2; nt++) {
        #pragma unroll
        for (int col = 0; col < 2; col++) {
            float F[2][2], V[2][2];          // [mt][half]
            #pragma unroll
            for (int mt = 0; mt < 2; mt++)
                #pragma unroll
                for (int hf = 0; hf < 2; hf++) {
                    F[mt][hf] = fr[mt][nt][hf][col];
                    V[mt][hf] = vr[mt][nt][hf][col];
                }
            // 3 xor-shuffle rounds over r8 (consecutive t within runs of 8)
            #pragma unroll
            for (int s = 0; s < 3; s++) {
                const int msk = 4 << s;
                const bool up = (lane & msk) != 0;   // higher r8 = later t
                #pragma unroll
                for (int mt = 0; mt < 2; mt++)
                    #pragma unroll
                    for (int hf = 0; hf < 2; hf++) {
                        float Fo = __shfl_xor_sync(0xFFFFFFFFu, F[mt][hf], msk);
                        float Vo = __shfl_xor_sync(0xFFFFFFFFu, V[mt][hf], msk);
                        float FL = up ? Fo : F[mt][hf];
                        float VL = up ? Vo : V[mt][hf];
                        float FH = up ? F[mt][hf] : Fo;
                        float VH = up ? V[mt][hf] : Vo;
                        F[mt][hf] = FL * FH;
                        V[mt][hf] = fmaf(VL, FH, VH);
                    }
            }
            // within thread, t order: (mt=0,hf=0),(0,1),(1,0),(1,1)
            float F01 = F[0][0] * F[0][1];
            float V01 = fmaf(V[0][0], F[0][1], V[0][1]);
            float F23 = F[1][0] * F[1][1];
            float V23 = fmaf(V[1][0], F[1][1], V[1][1]);
            float Fw = F01 * F23;
            float Vw = fmaf(V01, F23, V23);   // per-warp run of 32 t
            if (lane < 4) {
                int ch = wn * 16 + nt * 8 + 2 * lane + col;
                sF[wm * 32 + ch] = Fw;
                sV[wm * 32 + ch] = Vw;
            }
        }
    }
    __syncthreads();
    if (tid < 64) {                          // 2 chunks x 32 channels
        const int ch = tid & 31, p = tid >> 5;
        float F1 = sF[(2*p)   * 32 + ch], V1 = sV[(2*p)   * 32 + ch];
        float F2 = sF[(2*p+1) * 32 + ch], V2 = sV[(2*p+1) * 32 + ch];
        const int b = m0 >> 13;                        // m0 / TT
        const int chunk = ((m0 & (TT - 1)) >> 6) + p;  // t0/64 + p
        // transposed layout: [channel][chunk]
        const size_t o = (size_t)(b * HH + h0 + ch) * NC + chunk;
        g_cF[o] = F1 * F2;
        g_cV[o] = fmaf(V1, F2, V2);
    }
}

// ---------------------------------------------------------------------------
// Kernel 3: PARALLEL cross-chunk scan (coalesced aggregates)
// ---------------------------------------------------------------------------
__global__ __launch_bounds__(128)
void scan_top_kernel(const float* __restrict__ h0, float* __restrict__ out) {
    const int ch = blockIdx.x;
    const int b = ch >> 9, hh = ch & (HH - 1);
    const int c = threadIdx.x;             // chunk 0..127
    const int lane = c & 31, w = c >> 5;
    __shared__ float sF[4], sV[4];

    float x = h0[(size_t)b * HH + hh];
    float h = (x >= 0.f) ? (x + 0.5f) : __fdividef(1.f, 1.f + __expf(-x));
    if (c == 0) out[(size_t)b * (TT + 1) * HH + hh] = h;

    const size_t oa = (size_t)ch * NC + c;   // coalesced along threadIdx
    float F = g_cF[oa], V = g_cV[oa];

    #pragma unroll
    for (int s = 1; s < 32; s <<= 1) {
        float Fo = __shfl_up_sync(0xFFFFFFFFu, F, s);
        float Vo = __shfl_up_sync(0xFFFFFFFFu, V, s);
        if (lane >= s) { V = fmaf(Vo, F, V); F = Fo * F; }
    }
    if (lane == 31) { sF[w] = F; sV[w] = V; }
    __syncthreads();

    float Pf = 1.f, Pv = 0.f;
    #pragma unroll
    for (int i = 0; i < 3; i++)
        if (w > i) { Pv = fmaf(Pv, sF[i], sV[i]); Pf = Pf * sF[i]; }

    float Fe = __shfl_up_sync(0xFFFFFFFFu, F, 1);
    float Ve = __shfl_up_sync(0xFFFFFFFFu, V, 1);
    if (lane == 0) { Fe = 1.f; Ve = 0.f; }

    float Fx = Pf * Fe;
    float Vx = fmaf(Pv, Fe, Ve);
    g_hin[(size_t)c * NCH + ch] = fmaf(Fx, h, Vx);   // [chunk][channel]
}

// ---------------------------------------------------------------------------
// Kernel 4: apply (scalar, 1024 blocks — measured floor)
// ---------------------------------------------------------------------------
__global__ __launch_bounds__(256)
void scan_apply_kernel(float* __restrict__ out) {
    const int ch = blockIdx.x * 256 + threadIdx.x;
    const int b = ch >> 9, hh = ch & (HH - 1);
    const int chunk = blockIdx.y;
    const int t0 = chunk * CL;
    const size_t gbase = ((size_t)b * TT + t0) * HH + hh;
    const size_t obase = ((size_t)b * (TT + 1) + t0 + 1) * HH + hh;

    float h = g_hin[(size_t)chunk * NCH + ch];
    #pragma unroll 8
    for (int t = 0; t < CL; t++) {
        float2 fv = __half22float2(g_fv[gbase + (size_t)t * HH]);
        h = fmaf(fv.x, h, fv.y);
        out[obase + (size_t)t * HH] = h;
    }
}

// ---------------------------------------------------------------------------
extern "C" void kernel_launch(void* const* d_in, const int* in_sizes, int n_in,
                              void* d_out, int out_size) {
    const float* x  = (const float*)d_in[0];
    const float* h0 = (const float*)d_in[1];
    const float* Wf = (const float*)d_in[2];
    const float* bf = (const float*)d_in[3];
    const float* Wi = (const float*)d_in[4];
    const float* bi = (const float*)d_in[5];
    const float* Wh = (const float*)d_in[6];
    const float* bh = (const float*)d_in[7];
    float* out = (float*)d_out;

    cudaFuncSetAttribute(gemm_mma_kernel,
                         cudaFuncAttributeMaxDynamicSharedMemorySize, GEMM_SMEM);

    cvt_x_kernel<<<(size_t)M_TOTAL * DD / 8 / 256, 256>>>(x);
    {
        dim3 g(DD / 32, HH / 32, 3);
        split_w_kernel<<<g, dim3(32, 8)>>>(Wf, Wi, Wh);
    }
    {
        dim3 g(HH / 32, M_TOTAL / 128);    // (16, 256)
        gemm_mma_kernel<<<g, 256, GEMM_SMEM>>>(bf, bi, bh);
    }
    scan_top_kernel<<<NCH, 128>>>(h0, out);
    scan_apply_kernel<<<dim3(NCH / 256, NC), 256>>>(out);  // (8, 128)
}